// round 7
// baseline (speedup 1.0000x reference)
#include <cuda_runtime.h>
#include <math.h>

// Problem constants (B=4, F=100, n_peaks=16, W=H=64)
#define B_SZ 4
#define F_SZ 100
#define NP 16
#define PIX 4096
#define TPB 128
#define NFC 8                 // 4x13 + 4x12 = 100 -> 1024 CTAs = one wave @ occ 7
#define FCMAX 13

#define FLT_EPS_F 1.1920929e-7f
#define EXP_S2LD   59.066666f       // exp(sqrt(2*ln(4096)))
#define LOG_NPEAKS 2.7725887f       // ln(16)

#define MAG_COUNT ((size_t)B_SZ * F_SZ * PIX)   // 1,638,400
#define DIR_OFF   MAG_COUNT
#define AUX_OFF   (3 * MAG_COUNT)               // 4,915,200

#define NROWS (B_SZ * F_SZ)                     // 400

typedef unsigned long long u64t;

__device__ float       g_part[512];             // per-(b,p) eighth sums of exp(2x)
__device__ ulonglong2  g_yz[NROWS * NP];        // {(cy,cy),(cz,cz)} packed f32x2
__device__ u64t        g_cxp[NROWS * 8];        // (cx_2j, cx_2j+1) packed
__device__ float       g_bias[NROWS];           // pre-halved interp bias

// ---- f32x2 packed helpers (sm_100a) ----
__device__ __forceinline__ u64t pk2(float lo, float hi) {
    u64t r; asm("mov.b64 %0, {%1,%2};" : "=l"(r) : "f"(lo), "f"(hi)); return r;
}
__device__ __forceinline__ float2 upk2(u64t v) {
    float2 r; asm("mov.b64 {%0,%1}, %2;" : "=f"(r.x), "=f"(r.y) : "l"(v)); return r;
}
__device__ __forceinline__ u64t ffma2(u64t a, u64t b, u64t c) {
    u64t d; asm("fma.rn.f32x2 %0, %1, %2, %3;" : "=l"(d) : "l"(a), "l"(b), "l"(c)); return d;
}
__device__ __forceinline__ u64t fmul2(u64t a, u64t b) {
    u64t d; asm("mul.rn.f32x2 %0, %1, %2;" : "=l"(d) : "l"(a), "l"(b)); return d;
}
__device__ __forceinline__ u64t fadd2(u64t a, u64t b) {
    u64t d; asm("add.rn.f32x2 %0, %1, %2;" : "=l"(d) : "l"(a), "l"(b)); return d;
}

// ---------------------------------------------------------------------------
// Kernel 1: fused prep
//   blocks [0,512):    norm partial sums (bp = blk>>3, eighth = blk&7)
//   blocks [512,537):  response precompute (packed layouts) + bias
//   block  537:        aux_sparse
// ---------------------------------------------------------------------------
__global__ __launch_bounds__(TPB) void prep_kernel(
    const float* __restrict__ shapes,
    const float* __restrict__ resp,
    const float* __restrict__ freqs,
    float* __restrict__ out_aux)
{
    const int blk = blockIdx.x;
    const int tid = threadIdx.x;
    __shared__ float sh[TPB];

    if (blk < 512) {
        // ---- norm partials: 512 floats per block, 1 float4/thread ----
        const int bp = blk >> 3, oct = blk & 7;
        const int b = bp >> 4, p = bp & 15;
        const float4* x = (const float4*)(shapes + ((size_t)(b * 48 + p)) * PIX + oct * 512);
        float4 v = x[tid];
        float s = __expf(2.f * v.x) + __expf(2.f * v.y)
                + __expf(2.f * v.z) + __expf(2.f * v.w);
        sh[tid] = s; __syncthreads();
        if (tid < 64) sh[tid] += sh[tid + 64];
        __syncthreads();
        if (tid < 32) {
            float v2 = sh[tid] + sh[tid + 32];
            #pragma unroll
            for (int o = 16; o > 0; o >>= 1)
                v2 += __shfl_down_sync(0xffffffff, v2, o);
            if (tid == 0) g_part[blk] = v2;
        }
    } else if (blk < 537) {
        // ---- response precompute: 3200 pair-items, one shot ----
        const int idx = (blk - 512) * TPB + tid;    // [0, 3200)
        if (idx < NROWS * 8) {
            const int row = idx >> 3, j = idx & 7;
            const int p0 = 2 * j;
            const float* rb = resp + (size_t)row * 48;
            float er0 = __expf(rb[p0]),     er1 = __expf(rb[p0 + 1]);
            float tr0 = rb[16 + p0], ti0 = rb[32 + p0];
            float tr1 = rb[17 + p0], ti1 = rb[33 + p0];
            float i0 = rsqrtf(fmaxf(tr0 * tr0 + ti0 * ti0, FLT_EPS_F));
            float i1 = rsqrtf(fmaxf(tr1 * tr1 + ti1 * ti1, FLT_EPS_F));
            float y0 = er0 * tr0 * i0, z0 = er0 * ti0 * i0;
            float y1 = er1 * tr1 * i1, z1 = er1 * ti1 * i1;
            g_yz[row * NP + p0]     = make_ulonglong2(pk2(y0, y0), pk2(z0, z0));
            g_yz[row * NP + p0 + 1] = make_ulonglong2(pk2(y1, y1), pk2(z1, z1));
            g_cxp[row * 8 + j] = pk2(er0, er1);
            if (j == 0) {
                float fq  = freqs[row];
                float pos = fminf(fmaxf((fq + 1.0f) * 0.5f * 127.0f, 0.0f), 127.0f);
                float lof = floorf(pos);
                int   lo  = (int)lof;
                int   hi  = min(lo + 1, 127);
                float w   = pos - lof;
                const float k = 3.14159265358979323846f / 127.0f;
                float Tlo = cosf((float)lo * k) * 1.5f - 3.0f;
                float Thi = cosf((float)hi * k) * 1.5f - 3.0f;
                g_bias[row] = 0.5f * (Tlo * (1.0f - w) + Thi * w);
            }
        }
    } else {
        // ---- aux_sparse: 2 threads per (b,p), 50 f's each ----
        const int bp = tid & 63, g = tid >> 6;
        const int b = bp >> 4, p = bp & 15;
        float s = 0.f;
        #pragma unroll 5
        for (int f = g * 50; f < g * 50 + 50; f++)
            s += __expf(2.0f * resp[((size_t)b * F_SZ + f) * 48 + p]);
        sh[tid] = s; __syncthreads();
        if (tid < 64) {
            float st = sh[tid] + sh[tid + 64];
            float c  = 0.5f * logf(st);
            sh[tid]  = fmaxf(c, 0.0f) + log1pf(__expf(-fabsf(c)));
        }
        __syncthreads();
        if (tid < 32) {
            float v = sh[tid] + sh[tid + 32];
            #pragma unroll
            for (int o = 16; o > 0; o >>= 1)
                v += __shfl_down_sync(0xffffffff, v, o);
            if (tid == 0) *out_aux = v * (1.0f / 64.0f);
        }
    }
}

// ---------------------------------------------------------------------------
// Kernel 2: main field. f32x2-packed inner loop; single wave 1024 CTAs @ 7/SM.
// ---------------------------------------------------------------------------
__global__ __launch_bounds__(TPB, 7) void field_kernel(
    const float* __restrict__ shapes,
    float* __restrict__ out)
{
    const int b   = blockIdx.y;
    const int fc  = blockIdx.z;
    const int pix = blockIdx.x * TPB + threadIdx.x;
    const int tid = threadIdx.x;

    const int f0  = fc * 12 + min(fc, 4);
    const int len = (fc < 4) ? 13 : 12;

    __shared__ ulonglong2 sc_yz[FCMAX][NP];   // {(cy,cy),(cz,cz)}
    __shared__ u64t       scx[FCMAX][8];      // (cx_2j, cx_2j+1)
    __shared__ float      sbias[FCMAX];
    __shared__ float      sinvs[NP];

    const int row0 = b * F_SZ + f0;
    {
        const ulonglong2* gyz = g_yz + (size_t)row0 * NP;
        for (int i = tid; i < len * NP; i += TPB)
            ((ulonglong2*)sc_yz)[i] = gyz[i];
        const u64t* gcx = g_cxp + (size_t)row0 * 8;
        for (int i = tid; i < len * 8; i += TPB)
            ((u64t*)scx)[i] = gcx[i];
        if (tid < len) sbias[tid] = g_bias[row0 + tid];
        if (tid >= 32 && tid < 32 + NP) {
            const int p = tid - 32;
            const int g8 = (b * NP + p) * 8;
            float S = 0.f;
            #pragma unroll
            for (int k = 0; k < 8; k++) S += g_part[g8 + k];
            sinvs[p] = EXP_S2LD * rsqrtf(S);
        }
    }
    __syncthreads();

    // Per-pixel setup: X[p] = (Exr, Exi) packed; Ep2[j] = (E_2j, E_2j+1) packed
    u64t X[NP], Ep2[NP / 2];
    const float* sb = shapes + (size_t)b * 3 * NP * PIX + pix;
    {
        float Etmp[NP];
        #pragma unroll
        for (int p = 0; p < NP; p++) {
            float a  = sb[p * PIX];
            float e  = __expf(a) * sinvs[p];
            float r  = sb[(NP + p) * PIX];
            float im = sb[(2 * NP + p) * PIX];
            float inv = rsqrtf(fmaxf(r * r + im * im, FLT_EPS_F));
            Etmp[p] = e;
            X[p] = pk2(e * r * inv, e * im * inv);
        }
        #pragma unroll
        for (int j = 0; j < NP / 2; j++)
            Ep2[j] = pk2(Etmp[2 * j], Etmp[2 * j + 1]);
    }

    float* magp = out + (size_t)row0 * PIX + pix;
    float* dirp = out + DIR_OFF + (size_t)row0 * 2 * PIX + pix;

    #pragma unroll 2
    for (int lf = 0; lf < len; lf++) {
        u64t ua = 0ull, ub = 0ull, wa = 0ull, wb = 0ull;
        float wm_a = 0.f, wm_b = 0.f;
        #pragma unroll
        for (int j = 0; j < NP / 2; j++) {
            ulonglong2 c0 = sc_yz[lf][2 * j];
            ulonglong2 c1 = sc_yz[lf][2 * j + 1];
            ua = ffma2(X[2 * j],     c0.x, ua);
            wa = ffma2(X[2 * j],     c0.y, wa);
            ub = ffma2(X[2 * j + 1], c1.x, ub);
            wb = ffma2(X[2 * j + 1], c1.y, wb);
            float2 wf = upk2(fmul2(Ep2[j], scx[lf][j]));
            wm_a = fmaxf(wm_a, wf.x);
            wm_b = fmaxf(wm_b, wf.y);
        }
        float2 u = upk2(fadd2(ua, ub));   // (sum Exr*cy, sum Exi*cy)
        float2 w = upk2(fadd2(wa, wb));   // (sum Exr*cz, sum Exi*cz)
        float sr = u.x - w.y;
        float si = w.x + u.y;
        float wm = fmaxf(wm_a, wm_b);

        // ss = e^{2m} * (sr_shift^2 + si_shift^2 + eps)  with m = max_p mag
        float ss  = fmaf(sr, sr, fmaf(si, si, 0.001f * wm * wm));
        float inv = rsqrtf(ss);
        float ln  = 0.5f * __logf(ss);

        *magp = ln - LOG_NPEAKS + sbias[lf];
        dirp[0]   = sr * inv;
        dirp[PIX] = si * inv;
        magp += PIX;
        dirp += 2 * PIX;
    }
}

extern "C" void kernel_launch(void* const* d_in, const int* in_sizes, int n_in,
                              void* d_out, int out_size) {
    const float* shapes = (const float*)d_in[0];  // (4,3,16,64,64)
    const float* resp   = (const float*)d_in[1];  // (4,100,3,16)
    const float* freqs  = (const float*)d_in[2];  // (4,100)
    float* out = (float*)d_out;

    prep_kernel<<<538, TPB>>>(shapes, resp, freqs, out + AUX_OFF);
    dim3 grid(PIX / TPB, B_SZ, NFC);
    field_kernel<<<grid, TPB>>>(shapes, out);
}

// round 8
// speedup vs baseline: 1.0202x; 1.0202x over previous
#include <cuda_runtime.h>
#include <math.h>

// Problem constants (B=4, F=100, n_peaks=16, W=H=64)
#define B_SZ 4
#define F_SZ 100
#define NP 16
#define PIX 4096
#define TPB 128
#define NFC 9                 // 1x12 + 8x11 = 100 -> grid 1152 <= 148*8 one wave
#define FCMAX 12

#define FLT_EPS_F 1.1920929e-7f
#define EXP_S2LD   59.066666f       // exp(sqrt(2*ln(4096)))
#define LOG_NPEAKS 2.7725887f       // ln(16)

#define MAG_COUNT ((size_t)B_SZ * F_SZ * PIX)   // 1,638,400
#define DIR_OFF   MAG_COUNT
#define AUX_OFF   (3 * MAG_COUNT)               // 4,915,200

#define NROWS (B_SZ * F_SZ)                     // 400

__device__ float  g_part[512];                  // per-(b,p) eighth sums of exp(2x)
__device__ float4 g_c3[NROWS * 12];             // 48 floats/row: {cx,cy,cz} x 16 peaks, packed
__device__ float  g_bias[NROWS];                // pre-halved interp bias

// ---------------------------------------------------------------------------
// Kernel 1: fused prep
//   blocks [0,512):    norm partial sums (bp = blk>>3, eighth = blk&7)
//   blocks [512,562):  response precompute (packed-3 layout) + bias
//   block  562:        aux_sparse
// ---------------------------------------------------------------------------
__global__ __launch_bounds__(TPB) void prep_kernel(
    const float* __restrict__ shapes,
    const float* __restrict__ resp,
    const float* __restrict__ freqs,
    float* __restrict__ out_aux)
{
    const int blk = blockIdx.x;
    const int tid = threadIdx.x;
    __shared__ float sh[TPB];

    if (blk < 512) {
        // ---- norm partials: 512 floats per block, 1 float4/thread ----
        const int bp = blk >> 3, oct = blk & 7;
        const int b = bp >> 4, p = bp & 15;
        const float4* x = (const float4*)(shapes + ((size_t)(b * 48 + p)) * PIX + oct * 512);
        float4 v = x[tid];
        float s = __expf(2.f * v.x) + __expf(2.f * v.y)
                + __expf(2.f * v.z) + __expf(2.f * v.w);
        sh[tid] = s; __syncthreads();
        if (tid < 64) sh[tid] += sh[tid + 64];
        __syncthreads();
        if (tid < 32) {
            float v2 = sh[tid] + sh[tid + 32];
            #pragma unroll
            for (int o = 16; o > 0; o >>= 1)
                v2 += __shfl_down_sync(0xffffffff, v2, o);
            if (tid == 0) g_part[blk] = v2;
        }
    } else if (blk < 562) {
        // ---- response precompute: one (row, peak) item per thread ----
        const int idx = (blk - 512) * TPB + tid;    // [0, 6400)
        if (idx < NROWS * NP) {
            const int row = idx >> 4, p = idx & 15;
            const float* rb = resp + (size_t)row * 48;
            float er = __expf(rb[p]);
            float tr = rb[16 + p], ti = rb[32 + p];
            float inv = rsqrtf(fmaxf(tr * tr + ti * ti, FLT_EPS_F));
            float* dst = (float*)(g_c3 + (size_t)row * 12) + 3 * p;
            dst[0] = er;
            dst[1] = er * tr * inv;
            dst[2] = er * ti * inv;
            if (p == 0) {
                float fq  = freqs[row];
                float pos = fminf(fmaxf((fq + 1.0f) * 0.5f * 127.0f, 0.0f), 127.0f);
                float lof = floorf(pos);
                int   lo  = (int)lof;
                int   hi  = min(lo + 1, 127);
                float w   = pos - lof;
                const float k = 3.14159265358979323846f / 127.0f;
                float Tlo = cosf((float)lo * k) * 1.5f - 3.0f;
                float Thi = cosf((float)hi * k) * 1.5f - 3.0f;
                g_bias[row] = 0.5f * (Tlo * (1.0f - w) + Thi * w);
            }
        }
    } else {
        // ---- aux_sparse: 2 threads per (b,p), 50 f's each ----
        const int bp = tid & 63, g = tid >> 6;
        const int b = bp >> 4, p = bp & 15;
        float s = 0.f;
        #pragma unroll 5
        for (int f = g * 50; f < g * 50 + 50; f++)
            s += __expf(2.0f * resp[((size_t)b * F_SZ + f) * 48 + p]);
        sh[tid] = s; __syncthreads();
        if (tid < 64) {
            float st = sh[tid] + sh[tid + 64];
            float c  = 0.5f * logf(st);
            sh[tid]  = fmaxf(c, 0.0f) + log1pf(__expf(-fabsf(c)));
        }
        __syncthreads();
        if (tid < 32) {
            float v = sh[tid] + sh[tid + 32];
            #pragma unroll
            for (int o = 16; o > 0; o >>= 1)
                v += __shfl_down_sync(0xffffffff, v, o);
            if (tid == 0) *out_aux = v * (1.0f / 64.0f);
        }
    }
}

// ---------------------------------------------------------------------------
// 4 peaks from 3 float4s: {cx,cy,cz} triplets
// ---------------------------------------------------------------------------
#define PEAK(pi, CX, CY, CZ)                                              \
    {                                                                     \
        wm = fmaxf(wm, E[pi] * (CX));                                     \
        sr0 = fmaf(Exr[pi],  (CY), sr0); sr0 = fmaf(-Exi[pi], (CZ), sr0); \
        si0 = fmaf(Exr[pi],  (CZ), si0); si0 = fmaf(Exi[pi],  (CY), si0); \
    }
#define PEAK1(pi, CX, CY, CZ)                                             \
    {                                                                     \
        wm1 = fmaxf(wm1, E[pi] * (CX));                                   \
        sr1 = fmaf(Exr[pi],  (CY), sr1); sr1 = fmaf(-Exi[pi], (CZ), sr1); \
        si1 = fmaf(Exr[pi],  (CZ), si1); si1 = fmaf(Exi[pi],  (CY), si1); \
    }

// ---------------------------------------------------------------------------
// Kernel 2: main field. Scalar inner loop, packed-3 smem (12 LDS.128/freq),
// grid 1152 CTAs @ 8/SM = one wave.
// ---------------------------------------------------------------------------
__global__ __launch_bounds__(TPB, 8) void field_kernel(
    const float* __restrict__ shapes,
    float* __restrict__ out)
{
    const int b   = blockIdx.y;
    const int fc  = blockIdx.z;
    const int pix = blockIdx.x * TPB + threadIdx.x;
    const int tid = threadIdx.x;

    const int f0  = fc * 11 + min(fc, 1);       // chunk 0: 12, chunks 1..8: 11
    const int len = (fc < 1) ? 12 : 11;

    __shared__ float4 sc[FCMAX][12];            // 48 floats per freq
    __shared__ float  sbias[FCMAX];
    __shared__ float  sinvs[NP];

    const int row0 = b * F_SZ + f0;
    {
        const float4* gc = g_c3 + (size_t)row0 * 12;
        for (int i = tid; i < len * 12; i += TPB)
            ((float4*)sc)[i] = gc[i];
        if (tid < len) sbias[tid] = g_bias[row0 + tid];
        if (tid >= 32 && tid < 32 + NP) {
            const int p = tid - 32;
            const int g8 = (b * NP + p) * 8;
            float S = 0.f;
            #pragma unroll
            for (int k = 0; k < 8; k++) S += g_part[g8 + k];
            sinvs[p] = EXP_S2LD * rsqrtf(S);
        }
    }
    __syncthreads();

    // Per-pixel setup: E = exp(a)*invs, Exr/Exi = E * normalized spatial dir
    float E[NP], Exr[NP], Exi[NP];
    const float* sb = shapes + (size_t)b * 3 * NP * PIX + pix;
    #pragma unroll
    for (int p = 0; p < NP; p++) {
        float a  = sb[p * PIX];
        float e  = __expf(a) * sinvs[p];
        float r  = sb[(NP + p) * PIX];
        float im = sb[(2 * NP + p) * PIX];
        float inv = rsqrtf(fmaxf(r * r + im * im, FLT_EPS_F));
        E[p]   = e;
        Exr[p] = e * r * inv;
        Exi[p] = e * im * inv;
    }

    float* magp = out + (size_t)row0 * PIX + pix;
    float* dirp = out + DIR_OFF + (size_t)row0 * 2 * PIX + pix;

    #pragma unroll 2
    for (int lf = 0; lf < len; lf++) {
        float sr0 = 0.f, sr1 = 0.f, si0 = 0.f, si1 = 0.f, wm = 0.f, wm1 = 0.f;
        #pragma unroll
        for (int g = 0; g < 4; g++) {
            float4 v0 = sc[lf][3 * g];
            float4 v1 = sc[lf][3 * g + 1];
            float4 v2 = sc[lf][3 * g + 2];
            PEAK (4 * g,     v0.x, v0.y, v0.z);
            PEAK1(4 * g + 1, v0.w, v1.x, v1.y);
            PEAK (4 * g + 2, v1.z, v1.w, v2.x);
            PEAK1(4 * g + 3, v2.y, v2.z, v2.w);
        }
        float sr = sr0 + sr1, si = si0 + si1;
        float wmx = fmaxf(wm, wm1);
        // ss = e^{2m} * (sr_shift^2 + si_shift^2 + eps)  with m = max_p mag
        float ss  = fmaf(sr, sr, fmaf(si, si, 0.001f * wmx * wmx));
        float inv = rsqrtf(ss);
        float ln  = 0.5f * __logf(ss);

        *magp = ln - LOG_NPEAKS + sbias[lf];
        dirp[0]   = sr * inv;
        dirp[PIX] = si * inv;
        magp += PIX;
        dirp += 2 * PIX;
    }
}

extern "C" void kernel_launch(void* const* d_in, const int* in_sizes, int n_in,
                              void* d_out, int out_size) {
    const float* shapes = (const float*)d_in[0];  // (4,3,16,64,64)
    const float* resp   = (const float*)d_in[1];  // (4,100,3,16)
    const float* freqs  = (const float*)d_in[2];  // (4,100)
    float* out = (float*)d_out;

    prep_kernel<<<563, TPB>>>(shapes, resp, freqs, out + AUX_OFF);
    dim3 grid(PIX / TPB, B_SZ, NFC);
    field_kernel<<<grid, TPB>>>(shapes, out);
}

// round 9
// speedup vs baseline: 1.1235x; 1.1012x over previous
#include <cuda_runtime.h>
#include <math.h>

// Problem constants (B=4, F=100, n_peaks=16, W=H=64)
#define B_SZ 4
#define F_SZ 100
#define NP 16
#define PIX 4096
#define TPB 128
#define PPT 2                 // pixels per thread
#define NFC 9                 // 1x12 + 8x11 = 100; grid 16*4*9=576 <= 148*4 one wave
#define FCMAX 12

#define FLT_EPS_F 1.1920929e-7f
#define EXP_S2LD   59.066666f       // exp(sqrt(2*ln(4096)))
#define LOG_NPEAKS 2.7725887f       // ln(16)

#define MAG_COUNT ((size_t)B_SZ * F_SZ * PIX)   // 1,638,400
#define DIR_OFF   MAG_COUNT
#define AUX_OFF   (3 * MAG_COUNT)               // 4,915,200

#define NROWS (B_SZ * F_SZ)                     // 400

__device__ float  g_part[512];                  // per-(b,p) eighth sums of exp(2x)
__device__ float4 g_c[NROWS * NP];              // {cx, cy, cz, 0} per (row, peak)
__device__ float  g_bias[NROWS];                // pre-halved interp bias

// ---------------------------------------------------------------------------
// Kernel 1: fused prep
//   blocks [0,512):    norm partial sums (bp = blk>>3, eighth = blk&7)
//   blocks [512,562):  response precompute + bias
//   block  562:        aux_sparse (fully unrolled loads -> MLP ~50)
// ---------------------------------------------------------------------------
__global__ __launch_bounds__(TPB) void prep_kernel(
    const float* __restrict__ shapes,
    const float* __restrict__ resp,
    const float* __restrict__ freqs,
    float* __restrict__ out_aux)
{
    const int blk = blockIdx.x;
    const int tid = threadIdx.x;
    __shared__ float sh[TPB];

    if (blk < 512) {
        // ---- norm partials: 512 floats per block, 1 float4/thread ----
        const int bp = blk >> 3, oct = blk & 7;
        const int b = bp >> 4, p = bp & 15;
        const float4* x = (const float4*)(shapes + ((size_t)(b * 48 + p)) * PIX + oct * 512);
        float4 v = x[tid];
        float s = __expf(2.f * v.x) + __expf(2.f * v.y)
                + __expf(2.f * v.z) + __expf(2.f * v.w);
        sh[tid] = s; __syncthreads();
        if (tid < 64) sh[tid] += sh[tid + 64];
        __syncthreads();
        if (tid < 32) {
            float v2 = sh[tid] + sh[tid + 32];
            #pragma unroll
            for (int o = 16; o > 0; o >>= 1)
                v2 += __shfl_down_sync(0xffffffff, v2, o);
            if (tid == 0) g_part[blk] = v2;
        }
    } else if (blk < 562) {
        // ---- response precompute: one (row, peak) item per thread ----
        const int idx = (blk - 512) * TPB + tid;    // [0, 6400)
        if (idx < NROWS * NP) {
            const int row = idx >> 4, p = idx & 15;
            const float* rb = resp + (size_t)row * 48;
            float er = __expf(rb[p]);
            float tr = rb[16 + p], ti = rb[32 + p];
            float inv = rsqrtf(fmaxf(tr * tr + ti * ti, FLT_EPS_F));
            g_c[idx] = make_float4(er, er * tr * inv, er * ti * inv, 0.f);
            if (p == 0) {
                float fq  = freqs[row];
                float pos = fminf(fmaxf((fq + 1.0f) * 0.5f * 127.0f, 0.0f), 127.0f);
                float lof = floorf(pos);
                int   lo  = (int)lof;
                int   hi  = min(lo + 1, 127);
                float w   = pos - lof;
                const float k = 3.14159265358979323846f / 127.0f;
                float Tlo = cosf((float)lo * k) * 1.5f - 3.0f;
                float Thi = cosf((float)hi * k) * 1.5f - 3.0f;
                g_bias[row] = 0.5f * (Tlo * (1.0f - w) + Thi * w);
            }
        }
    } else {
        // ---- aux_sparse: 2 threads per (b,p), 50 f's each, FULL unroll ----
        const int bp = tid & 63, g = tid >> 6;
        const int b = bp >> 4, p = bp & 15;
        const float* base = resp + ((size_t)(b * F_SZ) + g * 50) * 48 + p;
        float s = 0.f;
        #pragma unroll
        for (int k = 0; k < 50; k++)
            s += __expf(2.0f * base[(size_t)k * 48]);
        sh[tid] = s; __syncthreads();
        if (tid < 64) {
            float st = sh[tid] + sh[tid + 64];
            float c  = 0.5f * logf(st);
            sh[tid]  = fmaxf(c, 0.0f) + log1pf(__expf(-fabsf(c)));
        }
        __syncthreads();
        if (tid < 32) {
            float v = sh[tid] + sh[tid + 32];
            #pragma unroll
            for (int o = 16; o > 0; o >>= 1)
                v += __shfl_down_sync(0xffffffff, v, o);
            if (tid == 0) *out_aux = v * (1.0f / 64.0f);
        }
    }
}

// ---------------------------------------------------------------------------
// Kernel 2: main field. 2 pixels/thread (float2 I/O), R5 smem layout,
// grid 576 CTAs @ 4/SM = one wave. 4 independent FFMA chains per warp.
// ---------------------------------------------------------------------------
__global__ __launch_bounds__(TPB, 4) void field_kernel(
    const float* __restrict__ shapes,
    float* __restrict__ out)
{
    const int b   = blockIdx.y;
    const int fc  = blockIdx.z;
    const int tid = threadIdx.x;
    const int pix = blockIdx.x * (TPB * PPT) + 2 * tid;

    const int f0  = fc * 11 + min(fc, 1);       // chunk 0: 12, chunks 1..8: 11
    const int len = (fc < 1) ? 12 : 11;

    __shared__ float4 sc[FCMAX][NP];            // {cx,cy,cz,0}
    __shared__ float  sbias[FCMAX];
    __shared__ float  sinvs[NP];

    const int row0 = b * F_SZ + f0;
    {
        const float4* gc = g_c + (size_t)row0 * NP;
        for (int i = tid; i < len * NP; i += TPB)
            ((float4*)sc)[i] = gc[i];
        if (tid < len) sbias[tid] = g_bias[row0 + tid];
        if (tid >= 32 && tid < 32 + NP) {
            const int p = tid - 32;
            const int g8 = (b * NP + p) * 8;
            float S = 0.f;
            #pragma unroll
            for (int k = 0; k < 8; k++) S += g_part[g8 + k];
            sinvs[p] = EXP_S2LD * rsqrtf(S);
        }
    }
    __syncthreads();

    // Per-pixel-pair setup
    float E0[NP], xr0[NP], xi0[NP];
    float E1[NP], xr1[NP], xi1[NP];
    const float* sb = shapes + (size_t)b * 3 * NP * PIX + pix;
    #pragma unroll
    for (int p = 0; p < NP; p++) {
        float2 a  = *(const float2*)(sb + p * PIX);
        float2 r  = *(const float2*)(sb + (NP + p) * PIX);
        float2 im = *(const float2*)(sb + (2 * NP + p) * PIX);
        float iv = sinvs[p];
        float e0 = __expf(a.x) * iv;
        float e1 = __expf(a.y) * iv;
        float n0 = rsqrtf(fmaxf(r.x * r.x + im.x * im.x, FLT_EPS_F));
        float n1 = rsqrtf(fmaxf(r.y * r.y + im.y * im.y, FLT_EPS_F));
        E0[p] = e0; xr0[p] = e0 * r.x * n0; xi0[p] = e0 * im.x * n0;
        E1[p] = e1; xr1[p] = e1 * r.y * n1; xi1[p] = e1 * im.y * n1;
    }

    float* magp = out + (size_t)row0 * PIX + pix;
    float* dirp = out + DIR_OFF + (size_t)row0 * 2 * PIX + pix;

    for (int lf = 0; lf < len; lf++) {
        float sr0 = 0.f, si0 = 0.f, wm0 = 0.f;
        float sr1 = 0.f, si1 = 0.f, wm1 = 0.f;
        #pragma unroll
        for (int p = 0; p < NP; p++) {
            float4 c = sc[lf][p];
            wm0 = fmaxf(wm0, E0[p] * c.x);
            sr0 = fmaf(xr0[p],  c.y, sr0); sr0 = fmaf(-xi0[p], c.z, sr0);
            si0 = fmaf(xr0[p],  c.z, si0); si0 = fmaf(xi0[p],  c.y, si0);
            wm1 = fmaxf(wm1, E1[p] * c.x);
            sr1 = fmaf(xr1[p],  c.y, sr1); sr1 = fmaf(-xi1[p], c.z, sr1);
            si1 = fmaf(xr1[p],  c.z, si1); si1 = fmaf(xi1[p],  c.y, si1);
        }
        // ss = e^{2m} * (sr'^2 + si'^2 + eps),  m = max_p mag
        float ss0  = fmaf(sr0, sr0, fmaf(si0, si0, 0.001f * wm0 * wm0));
        float ss1  = fmaf(sr1, sr1, fmaf(si1, si1, 0.001f * wm1 * wm1));
        float iv0 = rsqrtf(ss0), iv1 = rsqrtf(ss1);
        float bias = sbias[lf];
        float2 mg = make_float2(0.5f * __logf(ss0) - LOG_NPEAKS + bias,
                                0.5f * __logf(ss1) - LOG_NPEAKS + bias);
        float2 dr = make_float2(sr0 * iv0, sr1 * iv1);
        float2 di = make_float2(si0 * iv0, si1 * iv1);

        *(float2*)magp         = mg;
        *(float2*)dirp         = dr;
        *(float2*)(dirp + PIX) = di;
        magp += PIX;
        dirp += 2 * PIX;
    }
}

extern "C" void kernel_launch(void* const* d_in, const int* in_sizes, int n_in,
                              void* d_out, int out_size) {
    const float* shapes = (const float*)d_in[0];  // (4,3,16,64,64)
    const float* resp   = (const float*)d_in[1];  // (4,100,3,16)
    const float* freqs  = (const float*)d_in[2];  // (4,100)
    float* out = (float*)d_out;

    prep_kernel<<<563, TPB>>>(shapes, resp, freqs, out + AUX_OFF);
    dim3 grid(PIX / (TPB * PPT), B_SZ, NFC);
    field_kernel<<<grid, TPB>>>(shapes, out);
}

// round 10
// speedup vs baseline: 1.1352x; 1.0104x over previous
#include <cuda_runtime.h>
#include <math.h>

// Problem constants (B=4, F=100, n_peaks=16, W=H=64)
#define B_SZ 4
#define F_SZ 100
#define NP 16
#define PIX 4096
#define TPB 128
#define PPT 2                 // pixels per thread
#define NFC 9                 // 1x12 + 8x11 = 100; grid 16*4*9=576 <= 148*4 one wave
#define FCMAX 12

#define FLT_EPS_F 1.1920929e-7f
#define EXP_S2LD   59.066666f       // exp(sqrt(2*ln(4096)))
#define LOG_NPEAKS 2.7725887f       // ln(16)

#define MAG_COUNT ((size_t)B_SZ * F_SZ * PIX)   // 1,638,400
#define DIR_OFF   MAG_COUNT
#define AUX_OFF   (3 * MAG_COUNT)               // 4,915,200

#define NROWS (B_SZ * F_SZ)                     // 400

__device__ float  g_part[512];                  // per-(b,p) eighth sums of exp(2x)
__device__ float4 g_c[NROWS * NP];              // {cx, cy, cz, 0} per (row, peak)
__device__ float  g_bias[NROWS];                // pre-halved interp bias

// ---------------------------------------------------------------------------
// Kernel 1: fused prep
//   blocks [0,512):    norm partial sums (bp = blk>>3, eighth = blk&7)
//   blocks [512,562):  response precompute + bias
//   block  562:        aux_sparse (fully unrolled loads -> MLP ~50)
// ---------------------------------------------------------------------------
__global__ __launch_bounds__(TPB) void prep_kernel(
    const float* __restrict__ shapes,
    const float* __restrict__ resp,
    const float* __restrict__ freqs,
    float* __restrict__ out_aux)
{
    const int blk = blockIdx.x;
    const int tid = threadIdx.x;
    __shared__ float sh[TPB];

    if (blk < 512) {
        // ---- norm partials: 512 floats per block, 1 float4/thread ----
        const int bp = blk >> 3, oct = blk & 7;
        const int b = bp >> 4, p = bp & 15;
        const float4* x = (const float4*)(shapes + ((size_t)(b * 48 + p)) * PIX + oct * 512);
        float4 v = x[tid];
        float s = __expf(2.f * v.x) + __expf(2.f * v.y)
                + __expf(2.f * v.z) + __expf(2.f * v.w);
        sh[tid] = s; __syncthreads();
        if (tid < 64) sh[tid] += sh[tid + 64];
        __syncthreads();
        if (tid < 32) {
            float v2 = sh[tid] + sh[tid + 32];
            #pragma unroll
            for (int o = 16; o > 0; o >>= 1)
                v2 += __shfl_down_sync(0xffffffff, v2, o);
            if (tid == 0) g_part[blk] = v2;
        }
    } else if (blk < 562) {
        // ---- response precompute: one (row, peak) item per thread ----
        const int idx = (blk - 512) * TPB + tid;    // [0, 6400)
        if (idx < NROWS * NP) {
            const int row = idx >> 4, p = idx & 15;
            const float* rb = resp + (size_t)row * 48;
            float er = __expf(rb[p]);
            float tr = rb[16 + p], ti = rb[32 + p];
            float inv = rsqrtf(fmaxf(tr * tr + ti * ti, FLT_EPS_F));
            g_c[idx] = make_float4(er, er * tr * inv, er * ti * inv, 0.f);
            if (p == 0) {
                float fq  = freqs[row];
                float pos = fminf(fmaxf((fq + 1.0f) * 0.5f * 127.0f, 0.0f), 127.0f);
                float lof = floorf(pos);
                int   lo  = (int)lof;
                int   hi  = min(lo + 1, 127);
                float w   = pos - lof;
                const float k = 3.14159265358979323846f / 127.0f;
                float Tlo = cosf((float)lo * k) * 1.5f - 3.0f;
                float Thi = cosf((float)hi * k) * 1.5f - 3.0f;
                g_bias[row] = 0.5f * (Tlo * (1.0f - w) + Thi * w);
            }
        }
    } else {
        // ---- aux_sparse: 2 threads per (b,p), 50 f's each, FULL unroll ----
        const int bp = tid & 63, g = tid >> 6;
        const int b = bp >> 4, p = bp & 15;
        const float* base = resp + ((size_t)(b * F_SZ) + g * 50) * 48 + p;
        float s = 0.f;
        #pragma unroll
        for (int k = 0; k < 50; k++)
            s += __expf(2.0f * base[(size_t)k * 48]);
        sh[tid] = s; __syncthreads();
        if (tid < 64) {
            float st = sh[tid] + sh[tid + 64];
            float c  = 0.5f * logf(st);
            sh[tid]  = fmaxf(c, 0.0f) + log1pf(__expf(-fabsf(c)));
        }
        __syncthreads();
        if (tid < 32) {
            float v = sh[tid] + sh[tid + 32];
            #pragma unroll
            for (int o = 16; o > 0; o >>= 1)
                v += __shfl_down_sync(0xffffffff, v, o);
            if (tid == 0) *out_aux = v * (1.0f / 64.0f);
        }
    }
}

// ---------------------------------------------------------------------------
// Kernel 2: main field. 2 pixels/thread (float2 I/O), R5 smem layout,
// grid 576 CTAs @ 4/SM = one wave. 4 independent FFMA chains per warp.
// ---------------------------------------------------------------------------
__global__ __launch_bounds__(TPB, 4) void field_kernel(
    const float* __restrict__ shapes,
    float* __restrict__ out)
{
    const int b   = blockIdx.y;
    const int fc  = blockIdx.z;
    const int tid = threadIdx.x;
    const int pix = blockIdx.x * (TPB * PPT) + 2 * tid;

    const int f0  = fc * 11 + min(fc, 1);       // chunk 0: 12, chunks 1..8: 11
    const int len = (fc < 1) ? 12 : 11;

    __shared__ float4 sc[FCMAX][NP];            // {cx,cy,cz,0}
    __shared__ float  sbias[FCMAX];
    __shared__ float  sinvs[NP];

    const int row0 = b * F_SZ + f0;
    {
        const float4* gc = g_c + (size_t)row0 * NP;
        for (int i = tid; i < len * NP; i += TPB)
            ((float4*)sc)[i] = gc[i];
        if (tid < len) sbias[tid] = g_bias[row0 + tid];
        if (tid >= 32 && tid < 32 + NP) {
            const int p = tid - 32;
            const int g8 = (b * NP + p) * 8;
            float S = 0.f;
            #pragma unroll
            for (int k = 0; k < 8; k++) S += g_part[g8 + k];
            sinvs[p] = EXP_S2LD * rsqrtf(S);
        }
    }
    __syncthreads();

    // Per-pixel-pair setup
    float E0[NP], xr0[NP], xi0[NP];
    float E1[NP], xr1[NP], xi1[NP];
    const float* sb = shapes + (size_t)b * 3 * NP * PIX + pix;
    #pragma unroll
    for (int p = 0; p < NP; p++) {
        float2 a  = *(const float2*)(sb + p * PIX);
        float2 r  = *(const float2*)(sb + (NP + p) * PIX);
        float2 im = *(const float2*)(sb + (2 * NP + p) * PIX);
        float iv = sinvs[p];
        float e0 = __expf(a.x) * iv;
        float e1 = __expf(a.y) * iv;
        float n0 = rsqrtf(fmaxf(r.x * r.x + im.x * im.x, FLT_EPS_F));
        float n1 = rsqrtf(fmaxf(r.y * r.y + im.y * im.y, FLT_EPS_F));
        E0[p] = e0; xr0[p] = e0 * r.x * n0; xi0[p] = e0 * im.x * n0;
        E1[p] = e1; xr1[p] = e1 * r.y * n1; xi1[p] = e1 * im.y * n1;
    }

    float* magp = out + (size_t)row0 * PIX + pix;
    float* dirp = out + DIR_OFF + (size_t)row0 * 2 * PIX + pix;

    for (int lf = 0; lf < len; lf++) {
        float sr0 = 0.f, si0 = 0.f, wm0 = 0.f;
        float sr1 = 0.f, si1 = 0.f, wm1 = 0.f;
        #pragma unroll
        for (int p = 0; p < NP; p++) {
            float4 c = sc[lf][p];
            wm0 = fmaxf(wm0, E0[p] * c.x);
            sr0 = fmaf(xr0[p],  c.y, sr0); sr0 = fmaf(-xi0[p], c.z, sr0);
            si0 = fmaf(xr0[p],  c.z, si0); si0 = fmaf(xi0[p],  c.y, si0);
            wm1 = fmaxf(wm1, E1[p] * c.x);
            sr1 = fmaf(xr1[p],  c.y, sr1); sr1 = fmaf(-xi1[p], c.z, sr1);
            si1 = fmaf(xr1[p],  c.z, si1); si1 = fmaf(xi1[p],  c.y, si1);
        }
        // ss = e^{2m} * (sr'^2 + si'^2 + eps),  m = max_p mag
        float ss0  = fmaf(sr0, sr0, fmaf(si0, si0, 0.001f * wm0 * wm0));
        float ss1  = fmaf(sr1, sr1, fmaf(si1, si1, 0.001f * wm1 * wm1));
        float iv0 = rsqrtf(ss0), iv1 = rsqrtf(ss1);
        float bias = sbias[lf];
        float2 mg = make_float2(0.5f * __logf(ss0) - LOG_NPEAKS + bias,
                                0.5f * __logf(ss1) - LOG_NPEAKS + bias);
        float2 dr = make_float2(sr0 * iv0, sr1 * iv1);
        float2 di = make_float2(si0 * iv0, si1 * iv1);

        *(float2*)magp         = mg;
        *(float2*)dirp         = dr;
        *(float2*)(dirp + PIX) = di;
        magp += PIX;
        dirp += 2 * PIX;
    }
}

extern "C" void kernel_launch(void* const* d_in, const int* in_sizes, int n_in,
                              void* d_out, int out_size) {
    const float* shapes = (const float*)d_in[0];  // (4,3,16,64,64)
    const float* resp   = (const float*)d_in[1];  // (4,100,3,16)
    const float* freqs  = (const float*)d_in[2];  // (4,100)
    float* out = (float*)d_out;

    prep_kernel<<<563, TPB>>>(shapes, resp, freqs, out + AUX_OFF);
    dim3 grid(PIX / (TPB * PPT), B_SZ, NFC);
    field_kernel<<<grid, TPB>>>(shapes, out);
}